// round 6
// baseline (speedup 1.0000x reference)
#include <cuda_runtime.h>
#include <cuda_fp16.h>
#include <math.h>
#include <stdint.h>

// Shapes fixed by dataset: B=32, T=1024, J=1024, H=2048
#define BB 32
#define TT 1024
#define JJ 1024
#define HH 2048
#define MM (BB*TT)   // 32768

// ---------------- scratch (device globals; no allocations allowed) ----------------
__device__ float  g_h [(size_t)MM * HH];      // pre-activation fp32
__device__ __half g_s16[(size_t)MM * HH];     // spikes fp16
__device__ int8_t g_s8 [(size_t)MM * HH];     // spikes s8
__device__ __half g_x0[(size_t)MM * JJ];      // x hi
__device__ __half g_x1[(size_t)MM * JJ];      // x lo
__device__ __half g_w1a[(size_t)HH * JJ], g_w1b[(size_t)HH * JJ];
__device__ int8_t g_q2[(size_t)HH * HH], g_q3[(size_t)JJ * HH];   // int8 weight terms
__device__ __half g_e2[(size_t)HH * HH], g_e3[(size_t)JJ * HH];   // residual*256 fp16
__device__ float  g_sc2[HH], g_sc3[JJ];                            // per-row scales
__device__ float  g_mu[HH], g_var[HH];

// ---------------- helpers ----------------
__device__ __forceinline__ void cpasync16(void* dst, const void* src) {
    unsigned sa = (unsigned)__cvta_generic_to_shared(dst);
    asm volatile("cp.async.cg.shared.global [%0], [%1], 16;\n" :: "r"(sa), "l"(src));
}
__device__ __forceinline__ void ldm4(uint32_t* r, const __half* p) {
    unsigned a = (unsigned)__cvta_generic_to_shared(p);
    asm volatile("ldmatrix.sync.aligned.m8n8.x4.shared.b16 {%0,%1,%2,%3}, [%4];"
                 : "=r"(r[0]), "=r"(r[1]), "=r"(r[2]), "=r"(r[3]) : "r"(a));
}
__device__ __forceinline__ void mma16816(float* c, const uint32_t* a, uint32_t b0, uint32_t b1) {
    asm volatile("mma.sync.aligned.m16n8k16.row.col.f32.f16.f16.f32 "
                 "{%0,%1,%2,%3},{%4,%5,%6,%7},{%8,%9},{%0,%1,%2,%3};"
                 : "+f"(c[0]), "+f"(c[1]), "+f"(c[2]), "+f"(c[3])
                 : "r"(a[0]), "r"(a[1]), "r"(a[2]), "r"(a[3]), "r"(b0), "r"(b1));
}
__device__ __forceinline__ void imma16832(int* c, const uint32_t* a, uint32_t b0, uint32_t b1) {
    asm volatile("mma.sync.aligned.m16n8k32.row.col.s32.s8.s8.s32 "
                 "{%0,%1,%2,%3},{%4,%5,%6,%7},{%8,%9},{%0,%1,%2,%3};"
                 : "+r"(c[0]), "+r"(c[1]), "+r"(c[2]), "+r"(c[3])
                 : "r"(a[0]), "r"(a[1]), "r"(a[2]), "r"(a[3]), "r"(b0), "r"(b1));
}

// ---------------- fp32 -> (hi, lo) fp16 split ----------------
__global__ void split_f32(const float* __restrict__ src,
                          __half* __restrict__ a, __half* __restrict__ b, size_t n)
{
    size_t i = (size_t)blockIdx.x * blockDim.x + threadIdx.x;
    if (i >= n) return;
    float v = src[i];
    __half hi = __float2half_rn(v);
    a[i] = hi;
    b[i] = __float2half_rn(v - __half2float(hi));
}

// ---------------- per-row weight quantization: W = s1*Q1 + E,  store E*256 fp16 ------
__global__ void quant_w(const float* __restrict__ W, int8_t* __restrict__ Q,
                        __half* __restrict__ E256, float* __restrict__ s1v, int K)
{
    const int n = blockIdx.x;
    const int tid = threadIdx.x;
    const float* w = W + (size_t)n * K;

    float m = 0.0f;
    for (int k = tid; k < K; k += 256) m = fmaxf(m, fabsf(w[k]));
    __shared__ float red[256];
    red[tid] = m; __syncthreads();
    for (int s = 128; s > 0; s >>= 1) {
        if (tid < s) red[tid] = fmaxf(red[tid], red[tid + s]);
        __syncthreads();
    }
    float mx = red[0];
    float s1 = (mx > 0.0f) ? mx / 127.0f : 1.0f;
    float inv = (mx > 0.0f) ? 127.0f / mx : 0.0f;
    if (tid == 0) s1v[n] = s1;

    int8_t* q = Q + (size_t)n * K;
    __half* e = E256 + (size_t)n * K;
    for (int k = tid; k < K; k += 256) {
        float v = w[k];
        int qi = __float2int_rn(v * inv);
        qi = qi > 127 ? 127 : (qi < -127 ? -127 : qi);
        q[k] = (int8_t)qi;
        e[k] = __float2half_rn((v - s1 * (float)qi) * 256.0f);
    }
}

// ---------------- fp16 tensor-core GEMM: C[M,N] (+)= A[M,K] * (sum_b B_b)[N,K]^T ----
#define TSH 40
#define ARRH (128*TSH)
#define ARRB (ARRH*2)

template<int NB>
__global__ __launch_bounds__(256, 2) void gemm_v2(
    const __half* __restrict__ A, const __half* __restrict__ B0, const __half* __restrict__ B1,
    float* __restrict__ C, int N, int K, int accum)
{
    constexpr int NARR = 1 + NB;
    constexpr uint32_t STAGEB = NARR * ARRB;

    extern __shared__ __half smem[];

    const int tid  = threadIdx.x;
    const int lane = tid & 31;
    const int warp = tid >> 5;
    const int wm   = warp >> 2;
    const int wn   = warp & 3;
    const int bm   = blockIdx.y * 128;
    const int bn   = blockIdx.x * 128;

    const __half* gbase[3];
    gbase[0] = A  + (size_t)bm * K;
    gbase[1] = B0 + (size_t)bn * K;
    if (NB == 2) gbase[2] = B1 + (size_t)bn * K;

    float acc[4][4][4];
#pragma unroll
    for (int i = 0; i < 4; i++)
#pragma unroll
        for (int j = 0; j < 4; j++)
#pragma unroll
            for (int k = 0; k < 4; k++) acc[i][j][k] = 0.0f;

    const int NK = K >> 5;

    auto load_stage = [&](int kt, int slot) {
        const int kb = kt << 5;
        char* sb = (char*)smem + (uint32_t)slot * STAGEB;
#pragma unroll
        for (int a = 0; a < NARR; a++) {
            const __half* g = gbase[a];
            char* sa = sb + a * ARRB;
#pragma unroll
            for (int c = tid; c < 512; c += 256) {
                int r = c >> 2, q = c & 3;
                cpasync16(sa + r * (TSH*2) + q * 16, g + (size_t)r * K + kb + q * 8);
            }
        }
        asm volatile("cp.async.commit_group;");
    };

    load_stage(0, 0);
    if (NK > 1) load_stage(1, 1);

    for (int kt = 0; kt < NK; kt++) {
        if (kt + 1 < NK) asm volatile("cp.async.wait_group 1;");
        else             asm volatile("cp.async.wait_group 0;");
        __syncthreads();

        if (kt + 2 < NK) load_stage(kt + 2, (kt + 2) % 3);

        const __half* sb = smem + (uint32_t)((kt % 3) * STAGEB / 2);
        const __half* tA  = sb;
        const __half* tB0 = sb + ARRH;
        const __half* tB1 = sb + 2 * ARRH;

#pragma unroll
        for (int k16 = 0; k16 < 32; k16 += 16) {
            uint32_t af[4][4];
            {
                int r  = wm * 64 + (lane & 7) + ((lane >> 3) & 1) * 8;
                int kc = k16 + (lane >> 4) * 8;
#pragma unroll
                for (int mt = 0; mt < 4; mt++)
                    ldm4(af[mt], tA + (r + mt * 16) * TSH + kc);
            }
#pragma unroll
            for (int p = 0; p < NB; p++) {
                const __half* tB = p ? tB1 : tB0;
                uint32_t bf[2][4];
                {
                    int r  = wn * 32 + (lane & 7) + (lane >> 4) * 8;
                    int kc = k16 + ((lane >> 3) & 1) * 8;
#pragma unroll
                    for (int g = 0; g < 2; g++)
                        ldm4(bf[g], tB + (r + g * 16) * TSH + kc);
                }
#pragma unroll
                for (int mt = 0; mt < 4; mt++)
#pragma unroll
                    for (int nt = 0; nt < 4; nt++)
                        mma16816(acc[mt][nt], af[mt],
                                 bf[nt >> 1][(nt & 1) * 2], bf[nt >> 1][(nt & 1) * 2 + 1]);
            }
        }
    }

#pragma unroll
    for (int mt = 0; mt < 4; mt++) {
#pragma unroll
        for (int nt = 0; nt < 4; nt++) {
            int row = bm + wm * 64 + mt * 16 + (lane >> 2);
            int col = bn + wn * 32 + nt * 8 + (lane & 3) * 2;
            float2* p0 = (float2*)(C + (size_t)row * N + col);
            float2* p1 = (float2*)(C + (size_t)(row + 8) * N + col);
            float2 v0 = make_float2(acc[mt][nt][0], acc[mt][nt][1]);
            float2 v1 = make_float2(acc[mt][nt][2], acc[mt][nt][3]);
            if (accum) {
                float2 o0 = *p0, o1 = *p1;
                v0.x += o0.x; v0.y += o0.y; v1.x += o1.x; v1.y += o1.y;
            }
            *p0 = v0; *p1 = v1;
        }
    }
}

// ---------------- int8 GEMM: C[M,N] = s1[n]*(A[M,K] . Q[N,K]^T) + C_old/256 ----------
// A in {0,1} s8, Q s8. CTA 128x128, k-block 64 bytes, 3-stage cp.async.
#define ISTR 80                 // bytes per smem row (64 + 16 pad)
#define IARR (128*ISTR)         // one 128-row array

__global__ __launch_bounds__(256, 2) void igemm(
    const int8_t* __restrict__ A, const int8_t* __restrict__ Q,
    const float* __restrict__ s1v, float* __restrict__ C, int N, int K)
{
    extern __shared__ char ism[];
    const int tid  = threadIdx.x;
    const int lane = tid & 31;
    const int warp = tid >> 5;
    const int wm   = warp >> 2;
    const int wn   = warp & 3;
    const int bm   = blockIdx.y * 128;
    const int bn   = blockIdx.x * 128;
    const int gr   = lane >> 2;
    const int c4   = (lane & 3) * 4;

    const int8_t* Ag = A + (size_t)bm * K;
    const int8_t* Qg = Q + (size_t)bn * K;

    int acc[4][4][4];
#pragma unroll
    for (int i = 0; i < 4; i++)
#pragma unroll
        for (int j = 0; j < 4; j++)
#pragma unroll
            for (int k = 0; k < 4; k++) acc[i][j][k] = 0;

    const int NK = K >> 6;

    auto load_stage = [&](int kt, int slot) {
        const int kb = kt << 6;
        char* sb = ism + (uint32_t)slot * (2 * IARR);
#pragma unroll
        for (int c = tid; c < 512; c += 256) {
            int r = c >> 2, q = c & 3;
            cpasync16(sb + r * ISTR + q * 16,        Ag + (size_t)r * K + kb + q * 16);
            cpasync16(sb + IARR + r * ISTR + q * 16, Qg + (size_t)r * K + kb + q * 16);
        }
        asm volatile("cp.async.commit_group;");
    };

    load_stage(0, 0);
    if (NK > 1) load_stage(1, 1);

    for (int kt = 0; kt < NK; kt++) {
        if (kt + 1 < NK) asm volatile("cp.async.wait_group 1;");
        else             asm volatile("cp.async.wait_group 0;");
        __syncthreads();

        if (kt + 2 < NK) load_stage(kt + 2, (kt + 2) % 3);

        const char* sb = ism + (uint32_t)((kt % 3) * (2 * IARR));
        const char* sA = sb;
        const char* sB = sb + IARR;

#pragma unroll
        for (int kk = 0; kk < 64; kk += 32) {
            uint32_t af[4][4], bf[4][2];
#pragma unroll
            for (int mt = 0; mt < 4; mt++) {
                const char* base = sA + (wm * 64 + mt * 16 + gr) * ISTR + kk + c4;
                af[mt][0] = *(const uint32_t*)(base);
                af[mt][1] = *(const uint32_t*)(base + 8 * ISTR);
                af[mt][2] = *(const uint32_t*)(base + 16);
                af[mt][3] = *(const uint32_t*)(base + 8 * ISTR + 16);
            }
#pragma unroll
            for (int nt = 0; nt < 4; nt++) {
                const char* base = sB + (wn * 32 + nt * 8 + gr) * ISTR + kk + c4;
                bf[nt][0] = *(const uint32_t*)(base);
                bf[nt][1] = *(const uint32_t*)(base + 16);
            }
#pragma unroll
            for (int mt = 0; mt < 4; mt++)
#pragma unroll
                for (int nt = 0; nt < 4; nt++)
                    imma16832(acc[mt][nt], af[mt], bf[nt][0], bf[nt][1]);
        }
    }

    // epilogue: C = s1[col]*acc + C_old * (1/256)
#pragma unroll
    for (int mt = 0; mt < 4; mt++) {
#pragma unroll
        for (int nt = 0; nt < 4; nt++) {
            int row = bm + wm * 64 + mt * 16 + gr;
            int col = bn + wn * 32 + nt * 8 + (lane & 3) * 2;
            float sc0 = s1v[col], sc1 = s1v[col + 1];
            float2* p0 = (float2*)(C + (size_t)row * N + col);
            float2* p1 = (float2*)(C + (size_t)(row + 8) * N + col);
            float2 o0 = *p0, o1 = *p1;
            float2 v0 = make_float2(sc0 * (float)acc[mt][nt][0] + o0.x * 0.00390625f,
                                    sc1 * (float)acc[mt][nt][1] + o0.y * 0.00390625f);
            float2 v1 = make_float2(sc0 * (float)acc[mt][nt][2] + o1.x * 0.00390625f,
                                    sc1 * (float)acc[mt][nt][3] + o1.y * 0.00390625f);
            *p0 = v0; *p1 = v1;
        }
    }
}

// ---------------- per-channel stats over 32768 rows (double accumulators) ----------------
__global__ void colstats(const float* __restrict__ h, int rows, int I)
{
    const int tx = threadIdx.x, ty = threadIdx.y;
    const int i = blockIdx.x * 32 + tx;

    double s = 0.0, q = 0.0;
    for (int r = ty; r < rows; r += 32) {
        double v = (double)h[(size_t)r * I + i];
        s += v; q += v * v;
    }
    __shared__ double sh_s[32][33], sh_q[32][33];
    sh_s[ty][tx] = s; sh_q[ty][tx] = q;
    __syncthreads();
    for (int off = 16; off > 0; off >>= 1) {
        if (ty < off) { sh_s[ty][tx] += sh_s[ty+off][tx]; sh_q[ty][tx] += sh_q[ty+off][tx]; }
        __syncthreads();
    }
    if (ty == 0) {
        double inv = 1.0 / (double)rows;
        double mu = sh_s[0][tx] * inv;
        g_mu[i]  = (float)mu;
        g_var[i] = (float)(sh_q[0][tx] * inv - mu * mu);
    }
}

// ---------------- BatchNorm + LIF scan (dual fp16 + s8 spike output) ----------------
__global__ void lif_scan_dual(const float* __restrict__ h,
                              const float* __restrict__ gamma, const float* __restrict__ bias,
                              const float* __restrict__ betap, const float* __restrict__ U0,
                              __half* __restrict__ S16, int8_t* __restrict__ S8,
                              int Bn, int T, int I)
{
    int idx = blockIdx.x * blockDim.x + threadIdx.x;
    if (idx >= Bn * I) return;
    int b = idx / I, i = idx - b * I;

    float m = g_mu[i];
    float rstd = (float)(1.0 / sqrt((double)g_var[i] + 1e-5));
    float g = gamma[i], bi = bias[i];
    float beta = (float)(1.0 / (1.0 + exp(-(double)betap[i])));
    float ombeta = 1.0f - beta;

    float U = U0[idx], Sv = 0.0f;
    const float* hp = h + (size_t)b * T * I + i;
    __half* sp16 = S16 + (size_t)b * T * I + i;
    int8_t* sp8  = S8  + (size_t)b * T * I + i;

    for (int t = 0; t < T; t++) {
        float x = ((hp[(size_t)t * I] - m) * rstd) * g + bi;
        U = beta * (U - Sv) + ombeta * x;
        Sv = (U >= 1.0f) ? 1.0f : 0.0f;
        sp16[(size_t)t * I] = __float2half_rn(Sv);
        sp8 [(size_t)t * I] = (int8_t)(Sv != 0.0f);
    }
}

__global__ void lif_scan_f32(const float* __restrict__ h,
                             const float* __restrict__ gamma, const float* __restrict__ bias,
                             const float* __restrict__ betap, const float* __restrict__ U0,
                             float* __restrict__ S, int Bn, int T, int I)
{
    int idx = blockIdx.x * blockDim.x + threadIdx.x;
    if (idx >= Bn * I) return;
    int b = idx / I, i = idx - b * I;

    float m = g_mu[i];
    float rstd = (float)(1.0 / sqrt((double)g_var[i] + 1e-5));
    float g = gamma[i], bi = bias[i];
    float beta = (float)(1.0 / (1.0 + exp(-(double)betap[i])));
    float ombeta = 1.0f - beta;

    float U = U0[idx], Sv = 0.0f;
    const float* hp = h + (size_t)b * T * I + i;
    float* sp = S + (size_t)b * T * I + i;

    for (int t = 0; t < T; t++) {
        float x = ((hp[(size_t)t * I] - m) * rstd) * g + bi;
        U = beta * (U - Sv) + ombeta * x;
        Sv = (U >= 1.0f) ? 1.0f : 0.0f;
        sp[(size_t)t * I] = Sv;
    }
}

// ---------------- driver ----------------
extern "C" void kernel_launch(void* const* d_in, const int* in_sizes, int n_in,
                              void* d_out, int out_size)
{
    const float* x      = (const float*)d_in[0];
    const float* W1     = (const float*)d_in[1];
    const float* beta1  = (const float*)d_in[2];
    const float* gamma1 = (const float*)d_in[3];
    const float* bias1  = (const float*)d_in[4];
    const float* U01    = (const float*)d_in[5];
    const float* W2     = (const float*)d_in[6];
    const float* beta2  = (const float*)d_in[7];
    const float* gamma2 = (const float*)d_in[8];
    const float* bias2  = (const float*)d_in[9];
    const float* U02    = (const float*)d_in[10];
    const float* W3     = (const float*)d_in[11];
    const float* beta3  = (const float*)d_in[12];
    const float* gamma3 = (const float*)d_in[13];
    const float* bias3  = (const float*)d_in[14];
    const float* U03    = (const float*)d_in[15];
    float* out = (float*)d_out;

    float *h, *sc2, *sc3; __half *s16, *x0, *x1, *w1a, *w1b, *e2, *e3;
    int8_t *s8, *q2, *q3;
    cudaGetSymbolAddress((void**)&h,   g_h);
    cudaGetSymbolAddress((void**)&s16, g_s16);
    cudaGetSymbolAddress((void**)&s8,  g_s8);
    cudaGetSymbolAddress((void**)&x0,  g_x0);
    cudaGetSymbolAddress((void**)&x1,  g_x1);
    cudaGetSymbolAddress((void**)&w1a, g_w1a);
    cudaGetSymbolAddress((void**)&w1b, g_w1b);
    cudaGetSymbolAddress((void**)&q2,  g_q2);
    cudaGetSymbolAddress((void**)&q3,  g_q3);
    cudaGetSymbolAddress((void**)&e2,  g_e2);
    cudaGetSymbolAddress((void**)&e3,  g_e3);
    cudaGetSymbolAddress((void**)&sc2, g_sc2);
    cudaGetSymbolAddress((void**)&sc3, g_sc3);

    const int SM2 = 3 * 3 * ARRB;   // fp16 NB=2: 92160 B
    const int SM1 = 3 * 2 * ARRB;   // fp16 NB=1: 61440 B
    const int SMI = 3 * 2 * IARR;   // int8: 61440 B
    cudaFuncSetAttribute(gemm_v2<2>, cudaFuncAttributeMaxDynamicSharedMemorySize, SM2);
    cudaFuncSetAttribute(gemm_v2<1>, cudaFuncAttributeMaxDynamicSharedMemorySize, SM1);
    cudaFuncSetAttribute(igemm,      cudaFuncAttributeMaxDynamicSharedMemorySize, SMI);

    // preprocessing
    split_f32<<<(unsigned)(((size_t)MM * JJ + 255) / 256), 256>>>(x,  x0,  x1,  (size_t)MM * JJ);
    split_f32<<<(unsigned)(((size_t)HH * JJ + 255) / 256), 256>>>(W1, w1a, w1b, (size_t)HH * JJ);
    quant_w<<<HH, 256>>>(W2, q2, e2, sc2, HH);
    quant_w<<<JJ, 256>>>(W3, q3, e3, sc3, HH);

    // ---- layer 1 (fp16 split, lo*lo dropped): h = x0@(W1a+W1b)^T + x1@W1a^T ----
    gemm_v2<2><<<dim3(HH / 128, MM / 128), 256, SM2>>>(x0, w1a, w1b, h, HH, JJ, 0);
    gemm_v2<1><<<dim3(HH / 128, MM / 128), 256, SM1>>>(x1, w1a, nullptr, h, HH, JJ, 1);
    colstats<<<HH / 32, dim3(32, 32)>>>(h, MM, HH);
    lif_scan_dual<<<(BB * HH + 255) / 256, 256>>>(h, gamma1, bias1, beta1, U01, s16, s8, BB, TT, HH);

    // ---- layer 2 (hybrid): h = S@E2'^T (fp16, E'=256E), then h = s1*(S@Q2^T) + h/256 ----
    gemm_v2<1><<<dim3(HH / 128, MM / 128), 256, SM1>>>(s16, e2, nullptr, h, HH, HH, 0);
    igemm<<<dim3(HH / 128, MM / 128), 256, SMI>>>(s8, q2, sc2, h, HH, HH);
    colstats<<<HH / 32, dim3(32, 32)>>>(h, MM, HH);
    lif_scan_dual<<<(BB * HH + 255) / 256, 256>>>(h, gamma2, bias2, beta2, U02, s16, s8, BB, TT, HH);

    // ---- layer 3 (hybrid) ----
    gemm_v2<1><<<dim3(JJ / 128, MM / 128), 256, SM1>>>(s16, e3, nullptr, h, JJ, HH, 0);
    igemm<<<dim3(JJ / 128, MM / 128), 256, SMI>>>(s8, q3, sc3, h, JJ, HH);
    colstats<<<JJ / 32, dim3(32, 32)>>>(h, MM, JJ);
    lif_scan_f32<<<(BB * JJ + 255) / 256, 256>>>(h, gamma3, bias3, beta3, U03, out, BB, TT, JJ);
}

// round 7
// speedup vs baseline: 1.7676x; 1.7676x over previous
#include <cuda_runtime.h>
#include <cuda_fp16.h>
#include <math.h>
#include <stdint.h>

// Shapes fixed by dataset: B=32, T=1024, J=1024, H=2048
#define BB 32
#define TT 1024
#define JJ 1024
#define HH 2048
#define MM (BB*TT)   // 32768

// ---------------- scratch (device globals; no allocations allowed) ----------------
__device__ float  g_h [(size_t)MM * HH];      // pre-activation fp32
__device__ __half g_s16[(size_t)MM * HH];     // spikes fp16
__device__ __half g_x0[(size_t)MM * JJ];      // x hi
__device__ __half g_x1[(size_t)MM * JJ];      // x lo
__device__ __half g_w1a[(size_t)HH * JJ], g_w1b[(size_t)HH * JJ];
__device__ __half g_w2a[(size_t)HH * HH], g_w2b[(size_t)HH * HH];
__device__ __half g_w3a[(size_t)JJ * HH], g_w3b[(size_t)JJ * HH];
__device__ double g_sum1[HH], g_sq1[HH];
__device__ double g_sum2[HH], g_sq2[HH];
__device__ double g_sum3[JJ], g_sq3[JJ];

// ---------------- helpers ----------------
__device__ __forceinline__ void cpasync16(void* dst, const void* src) {
    unsigned sa = (unsigned)__cvta_generic_to_shared(dst);
    asm volatile("cp.async.cg.shared.global [%0], [%1], 16;\n" :: "r"(sa), "l"(src));
}
__device__ __forceinline__ void ldm4(uint32_t* r, const __half* p) {
    unsigned a = (unsigned)__cvta_generic_to_shared(p);
    asm volatile("ldmatrix.sync.aligned.m8n8.x4.shared.b16 {%0,%1,%2,%3}, [%4];"
                 : "=r"(r[0]), "=r"(r[1]), "=r"(r[2]), "=r"(r[3]) : "r"(a));
}
__device__ __forceinline__ void mma16816(float* c, const uint32_t* a, uint32_t b0, uint32_t b1) {
    asm volatile("mma.sync.aligned.m16n8k16.row.col.f32.f16.f16.f32 "
                 "{%0,%1,%2,%3},{%4,%5,%6,%7},{%8,%9},{%0,%1,%2,%3};"
                 : "+f"(c[0]), "+f"(c[1]), "+f"(c[2]), "+f"(c[3])
                 : "r"(a[0]), "r"(a[1]), "r"(a[2]), "r"(a[3]), "r"(b0), "r"(b1));
}

// ---------------- prep kernels ----------------
__global__ void prep_x(const float* __restrict__ x)
{
    size_t i = (size_t)blockIdx.x * blockDim.x + threadIdx.x;
    if (i >= (size_t)MM * JJ) return;
    float v = x[i];
    __half hi = __float2half_rn(v);
    g_x0[i] = hi;
    g_x1[i] = __float2half_rn(v - __half2float(hi));
}

__global__ void prep_w(const float* __restrict__ W1, const float* __restrict__ W2,
                       const float* __restrict__ W3)
{
    size_t i = (size_t)blockIdx.x * blockDim.x + threadIdx.x;
    // zero stat accumulators
    if (i < HH) { g_sum1[i] = 0.0; g_sq1[i] = 0.0; g_sum2[i] = 0.0; g_sq2[i] = 0.0; }
    if (i < JJ) { g_sum3[i] = 0.0; g_sq3[i] = 0.0; }

    const size_t n1 = (size_t)HH * JJ;   // 2M
    const size_t n2 = (size_t)HH * HH;   // 4M
    const size_t n3 = (size_t)JJ * HH;   // 2M
    if (i < n1) {
        float v = W1[i]; __half h = __float2half_rn(v);
        g_w1a[i] = h; g_w1b[i] = __float2half_rn(v - __half2float(h));
    }
    if (i < n2) {
        float v = W2[i]; __half h = __float2half_rn(v);
        g_w2a[i] = h; g_w2b[i] = __float2half_rn(v - __half2float(h));
    }
    if (i < n3) {
        float v = W3[i]; __half h = __float2half_rn(v);
        g_w3a[i] = h; g_w3b[i] = __float2half_rn(v - __half2float(h));
    }
}

// ---------------- GEMM tiles ----------------
#define TSH 40
#define ARRH (128*TSH)
#define ARRB (ARRH*2)

// ======= layer-1 fused: C = A0*(B0+B1)^T + A1*B0^T =======
// 2-stage pipeline, 4 arrays (A0,A1,B0,B1) per stage = 80KB total.
__global__ __launch_bounds__(256, 2) void gemm_l1(
    const __half* __restrict__ A0g, const __half* __restrict__ A1g,
    const __half* __restrict__ B0g, const __half* __restrict__ B1g,
    float* __restrict__ C, int N, int K)
{
    extern __shared__ __half smem[];
    constexpr uint32_t STAGEB = 4 * ARRB;

    const int tid  = threadIdx.x;
    const int lane = tid & 31;
    const int warp = tid >> 5;
    const int wm   = warp >> 2;
    const int wn   = warp & 3;
    const int bm   = blockIdx.y * 128;
    const int bn   = blockIdx.x * 128;

    const __half* gbase[4];
    gbase[0] = A0g + (size_t)bm * K;
    gbase[1] = A1g + (size_t)bm * K;
    gbase[2] = B0g + (size_t)bn * K;
    gbase[3] = B1g + (size_t)bn * K;

    float acc[4][4][4];
#pragma unroll
    for (int i = 0; i < 4; i++)
#pragma unroll
        for (int j = 0; j < 4; j++)
#pragma unroll
            for (int k = 0; k < 4; k++) acc[i][j][k] = 0.0f;

    const int NK = K >> 5;

    auto load_stage = [&](int kt, int slot) {
        const int kb = kt << 5;
        char* sb = (char*)smem + (uint32_t)slot * STAGEB;
#pragma unroll
        for (int a = 0; a < 4; a++) {
            const __half* g = gbase[a];
            char* sa = sb + a * ARRB;
#pragma unroll
            for (int c = tid; c < 512; c += 256) {
                int r = c >> 2, q = c & 3;
                cpasync16(sa + r * (TSH*2) + q * 16, g + (size_t)r * K + kb + q * 8);
            }
        }
        asm volatile("cp.async.commit_group;");
    };

    load_stage(0, 0);

    for (int kt = 0; kt < NK; kt++) {
        if (kt + 1 < NK) {
            load_stage(kt + 1, (kt + 1) & 1);
            asm volatile("cp.async.wait_group 1;");
        } else {
            asm volatile("cp.async.wait_group 0;");
        }
        __syncthreads();

        const __half* sb = smem + (uint32_t)((kt & 1) * STAGEB / 2);
        const __half* tA0 = sb;
        const __half* tA1 = sb + ARRH;
        const __half* tB0 = sb + 2 * ARRH;
        const __half* tB1 = sb + 3 * ARRH;

#pragma unroll
        for (int k16 = 0; k16 < 32; k16 += 16) {
            const int ra = wm * 64 + (lane & 7) + ((lane >> 3) & 1) * 8;
            const int ka = k16 + (lane >> 4) * 8;
            const int rb = wn * 32 + (lane & 7) + (lane >> 4) * 8;
            const int kb2 = k16 + ((lane >> 3) & 1) * 8;

            uint32_t a0[4][4], a1[4][4], b0[2][4], b1[2][4];
#pragma unroll
            for (int mt = 0; mt < 4; mt++) ldm4(a0[mt], tA0 + (ra + mt * 16) * TSH + ka);
#pragma unroll
            for (int g = 0; g < 2; g++)  ldm4(b0[g], tB0 + (rb + g * 16) * TSH + kb2);
#pragma unroll
            for (int mt = 0; mt < 4; mt++)
#pragma unroll
                for (int nt = 0; nt < 4; nt++)
                    mma16816(acc[mt][nt], a0[mt], b0[nt >> 1][(nt & 1) * 2], b0[nt >> 1][(nt & 1) * 2 + 1]);

#pragma unroll
            for (int mt = 0; mt < 4; mt++) ldm4(a1[mt], tA1 + (ra + mt * 16) * TSH + ka);
#pragma unroll
            for (int mt = 0; mt < 4; mt++)
#pragma unroll
                for (int nt = 0; nt < 4; nt++)
                    mma16816(acc[mt][nt], a1[mt], b0[nt >> 1][(nt & 1) * 2], b0[nt >> 1][(nt & 1) * 2 + 1]);

#pragma unroll
            for (int g = 0; g < 2; g++)  ldm4(b1[g], tB1 + (rb + g * 16) * TSH + kb2);
#pragma unroll
            for (int mt = 0; mt < 4; mt++)
#pragma unroll
                for (int nt = 0; nt < 4; nt++)
                    mma16816(acc[mt][nt], a0[mt], b1[nt >> 1][(nt & 1) * 2], b1[nt >> 1][(nt & 1) * 2 + 1]);
        }
        __syncthreads();
    }

#pragma unroll
    for (int mt = 0; mt < 4; mt++) {
#pragma unroll
        for (int nt = 0; nt < 4; nt++) {
            int row = bm + wm * 64 + mt * 16 + (lane >> 2);
            int col = bn + wn * 32 + nt * 8 + (lane & 3) * 2;
            *(float2*)(C + (size_t)row * N + col)       = make_float2(acc[mt][nt][0], acc[mt][nt][1]);
            *(float2*)(C + (size_t)(row + 8) * N + col) = make_float2(acc[mt][nt][2], acc[mt][nt][3]);
        }
    }
}

// ======= layers 2/3: C = A*(B0+B1)^T, 3-stage =======
__global__ __launch_bounds__(256, 2) void gemm_v2(
    const __half* __restrict__ A, const __half* __restrict__ B0, const __half* __restrict__ B1,
    float* __restrict__ C, int N, int K)
{
    constexpr uint32_t STAGEB = 3 * ARRB;
    extern __shared__ __half smem[];

    const int tid  = threadIdx.x;
    const int lane = tid & 31;
    const int warp = tid >> 5;
    const int wm   = warp >> 2;
    const int wn   = warp & 3;
    const int bm   = blockIdx.y * 128;
    const int bn   = blockIdx.x * 128;

    const __half* gbase[3];
    gbase[0] = A  + (size_t)bm * K;
    gbase[1] = B0 + (size_t)bn * K;
    gbase[2] = B1 + (size_t)bn * K;

    float acc[4][4][4];
#pragma unroll
    for (int i = 0; i < 4; i++)
#pragma unroll
        for (int j = 0; j < 4; j++)
#pragma unroll
            for (int k = 0; k < 4; k++) acc[i][j][k] = 0.0f;

    const int NK = K >> 5;

    auto load_stage = [&](int kt, int slot) {
        const int kb = kt << 5;
        char* sb = (char*)smem + (uint32_t)slot * STAGEB;
#pragma unroll
        for (int a = 0; a < 3; a++) {
            const __half* g = gbase[a];
            char* sa = sb + a * ARRB;
#pragma unroll
            for (int c = tid; c < 512; c += 256) {
                int r = c >> 2, q = c & 3;
                cpasync16(sa + r * (TSH*2) + q * 16, g + (size_t)r * K + kb + q * 8);
            }
        }
        asm volatile("cp.async.commit_group;");
    };

    load_stage(0, 0);
    if (NK > 1) load_stage(1, 1);

    for (int kt = 0; kt < NK; kt++) {
        if (kt + 1 < NK) asm volatile("cp.async.wait_group 1;");
        else             asm volatile("cp.async.wait_group 0;");
        __syncthreads();

        if (kt + 2 < NK) load_stage(kt + 2, (kt + 2) % 3);

        const __half* sb = smem + (uint32_t)((kt % 3) * STAGEB / 2);
        const __half* tA  = sb;
        const __half* tB0 = sb + ARRH;
        const __half* tB1 = sb + 2 * ARRH;

#pragma unroll
        for (int k16 = 0; k16 < 32; k16 += 16) {
            uint32_t af[4][4];
            {
                int r  = wm * 64 + (lane & 7) + ((lane >> 3) & 1) * 8;
                int kc = k16 + (lane >> 4) * 8;
#pragma unroll
                for (int mt = 0; mt < 4; mt++)
                    ldm4(af[mt], tA + (r + mt * 16) * TSH + kc);
            }
#pragma unroll
            for (int p = 0; p < 2; p++) {
                const __half* tB = p ? tB1 : tB0;
                uint32_t bf[2][4];
                {
                    int r  = wn * 32 + (lane & 7) + (lane >> 4) * 8;
                    int kc = k16 + ((lane >> 3) & 1) * 8;
#pragma unroll
                    for (int g = 0; g < 2; g++)
                        ldm4(bf[g], tB + (r + g * 16) * TSH + kc);
                }
#pragma unroll
                for (int mt = 0; mt < 4; mt++)
#pragma unroll
                    for (int nt = 0; nt < 4; nt++)
                        mma16816(acc[mt][nt], af[mt],
                                 bf[nt >> 1][(nt & 1) * 2], bf[nt >> 1][(nt & 1) * 2 + 1]);
            }
        }
    }

#pragma unroll
    for (int mt = 0; mt < 4; mt++) {
#pragma unroll
        for (int nt = 0; nt < 4; nt++) {
            int row = bm + wm * 64 + mt * 16 + (lane >> 2);
            int col = bn + wn * 32 + nt * 8 + (lane & 3) * 2;
            *(float2*)(C + (size_t)row * N + col)       = make_float2(acc[mt][nt][0], acc[mt][nt][1]);
            *(float2*)(C + (size_t)(row + 8) * N + col) = make_float2(acc[mt][nt][2], acc[mt][nt][3]);
        }
    }
}

// ---------------- per-channel stats: 8 row-chunks, double atomics ----------------
__global__ void colstats(const float* __restrict__ h, double* __restrict__ sum,
                         double* __restrict__ sq, int rows, int I)
{
    const int tx = threadIdx.x, ty = threadIdx.y;
    const int i = blockIdx.x * 32 + tx;
    const int chunk = blockIdx.y;                 // 0..7
    const int r0 = chunk * (rows >> 3);

    double s = 0.0, q = 0.0;
    for (int r = r0 + ty; r < r0 + (rows >> 3); r += 32) {
        double v = (double)h[(size_t)r * I + i];
        s += v; q += v * v;
    }
    __shared__ double sh_s[32][33], sh_q[32][33];
    sh_s[ty][tx] = s; sh_q[ty][tx] = q;
    __syncthreads();
    for (int off = 16; off > 0; off >>= 1) {
        if (ty < off) { sh_s[ty][tx] += sh_s[ty+off][tx]; sh_q[ty][tx] += sh_q[ty+off][tx]; }
        __syncthreads();
    }
    if (ty == 0) {
        atomicAdd(&sum[i], sh_s[0][tx]);
        atomicAdd(&sq[i],  sh_q[0][tx]);
    }
}

// ---------------- BatchNorm + LIF scan (finalizes stats from sums) ----------------
template <typename OutT>
__global__ void lif_scan(const float* __restrict__ h,
                         const double* __restrict__ sum, const double* __restrict__ sq,
                         const float* __restrict__ gamma, const float* __restrict__ bias,
                         const float* __restrict__ betap, const float* __restrict__ U0,
                         OutT* __restrict__ S, int Bn, int T, int I)
{
    int idx = blockIdx.x * blockDim.x + threadIdx.x;
    if (idx >= Bn * I) return;
    int b = idx / I, i = idx - b * I;

    const double inv = 1.0 / (double)(Bn * T);
    double mu_d = sum[i] * inv;
    double var_d = sq[i] * inv - mu_d * mu_d;
    float m = (float)mu_d;
    float rstd = (float)(1.0 / sqrt(var_d + 1e-5));
    float g = gamma[i], bi = bias[i];
    float beta = (float)(1.0 / (1.0 + exp(-(double)betap[i])));
    float ombeta = 1.0f - beta;

    float U = U0[idx], Sv = 0.0f;
    const float* hp = h + (size_t)b * T * I + i;
    OutT* sp = S + (size_t)b * T * I + i;

    for (int t = 0; t < T; t++) {
        float x = ((hp[(size_t)t * I] - m) * rstd) * g + bi;
        U = beta * (U - Sv) + ombeta * x;
        Sv = (U >= 1.0f) ? 1.0f : 0.0f;
        sp[(size_t)t * I] = (OutT)Sv;
    }
}

// ---------------- driver ----------------
extern "C" void kernel_launch(void* const* d_in, const int* in_sizes, int n_in,
                              void* d_out, int out_size)
{
    const float* x      = (const float*)d_in[0];
    const float* W1     = (const float*)d_in[1];
    const float* beta1  = (const float*)d_in[2];
    const float* gamma1 = (const float*)d_in[3];
    const float* bias1  = (const float*)d_in[4];
    const float* U01    = (const float*)d_in[5];
    const float* W2     = (const float*)d_in[6];
    const float* beta2  = (const float*)d_in[7];
    const float* gamma2 = (const float*)d_in[8];
    const float* bias2  = (const float*)d_in[9];
    const float* U02    = (const float*)d_in[10];
    const float* W3     = (const float*)d_in[11];
    const float* beta3  = (const float*)d_in[12];
    const float* gamma3 = (const float*)d_in[13];
    const float* bias3  = (const float*)d_in[14];
    const float* U03    = (const float*)d_in[15];
    float* out = (float*)d_out;

    float *h; __half *s16, *x0, *x1, *w1a, *w1b, *w2a, *w2b, *w3a, *w3b;
    double *sum1, *sq1, *sum2, *sq2, *sum3, *sq3;
    cudaGetSymbolAddress((void**)&h,   g_h);
    cudaGetSymbolAddress((void**)&s16, g_s16);
    cudaGetSymbolAddress((void**)&x0,  g_x0);
    cudaGetSymbolAddress((void**)&x1,  g_x1);
    cudaGetSymbolAddress((void**)&w1a, g_w1a);
    cudaGetSymbolAddress((void**)&w1b, g_w1b);
    cudaGetSymbolAddress((void**)&w2a, g_w2a);
    cudaGetSymbolAddress((void**)&w2b, g_w2b);
    cudaGetSymbolAddress((void**)&w3a, g_w3a);
    cudaGetSymbolAddress((void**)&w3b, g_w3b);
    cudaGetSymbolAddress((void**)&sum1, g_sum1);
    cudaGetSymbolAddress((void**)&sq1,  g_sq1);
    cudaGetSymbolAddress((void**)&sum2, g_sum2);
    cudaGetSymbolAddress((void**)&sq2,  g_sq2);
    cudaGetSymbolAddress((void**)&sum3, g_sum3);
    cudaGetSymbolAddress((void**)&sq3,  g_sq3);

    const int SML1 = 2 * 4 * ARRB;   // 81920 B
    const int SMV2 = 3 * 3 * ARRB;   // 92160 B
    cudaFuncSetAttribute(gemm_l1, cudaFuncAttributeMaxDynamicSharedMemorySize, SML1);
    cudaFuncSetAttribute(gemm_v2, cudaFuncAttributeMaxDynamicSharedMemorySize, SMV2);

    // 0: split x
    prep_x<<<(unsigned)(((size_t)MM * JJ + 255) / 256), 256>>>(x);
    // 1: split W1,W2,W3 + zero stat sums
    prep_w<<<(unsigned)(((size_t)HH * HH + 255) / 256), 256>>>(W1, W2, W3);

    // 2: layer-1 fused GEMM
    gemm_l1<<<dim3(HH / 128, MM / 128), 256, SML1>>>(x0, x1, w1a, w1b, h, HH, JJ);
    // 3,4
    colstats<<<dim3(HH / 32, 8), dim3(32, 32)>>>(h, sum1, sq1, MM, HH);
    lif_scan<__half><<<(BB * HH + 255) / 256, 256>>>(h, sum1, sq1, gamma1, bias1, beta1, U01, s16, BB, TT, HH);

    // 5: layer-2 GEMM (ncu -s 5 captures this)
    gemm_v2<<<dim3(HH / 128, MM / 128), 256, SMV2>>>(s16, w2a, w2b, h, HH, HH);
    // 6,7
    colstats<<<dim3(HH / 32, 8), dim3(32, 32)>>>(h, sum2, sq2, MM, HH);
    lif_scan<__half><<<(BB * HH + 255) / 256, 256>>>(h, sum2, sq2, gamma2, bias2, beta2, U02, s16, BB, TT, HH);

    // 8: layer-3 GEMM
    gemm_v2<<<dim3(JJ / 128, MM / 128), 256, SMV2>>>(s16, w3a, w3b, h, JJ, HH);
    // 9,10
    colstats<<<dim3(JJ / 32, 8), dim3(32, 32)>>>(h, sum3, sq3, MM, JJ);
    lif_scan<float><<<(BB * JJ + 255) / 256, 256>>>(h, sum3, sq3, gamma3, bias3, beta3, U03, out, BB, TT, JJ);
}

// round 8
// speedup vs baseline: 2.2105x; 1.2506x over previous
#include <cuda_runtime.h>
#include <cuda_fp16.h>
#include <math.h>
#include <stdint.h>

// Shapes fixed by dataset: B=32, T=1024, J=1024, H=2048
#define BB 32
#define TT 1024
#define JJ 1024
#define HH 2048
#define MM (BB*TT)   // 32768

// ---------------- scratch (device globals; no allocations allowed) ----------------
__device__ float  g_h [(size_t)MM * HH];      // pre-activation fp32
__device__ __half g_s16[(size_t)MM * HH];     // spikes fp16
__device__ __half g_x0[(size_t)MM * JJ];      // x hi
__device__ __half g_x1[(size_t)MM * JJ];      // x lo
__device__ __half g_w1a[(size_t)HH * JJ], g_w1b[(size_t)HH * JJ];
__device__ __half g_w2a[(size_t)HH * HH], g_w2b[(size_t)HH * HH];
__device__ __half g_w3a[(size_t)JJ * HH], g_w3b[(size_t)JJ * HH];
__device__ double g_sum1[HH], g_sq1[HH];
__device__ double g_sum2[HH], g_sq2[HH];
__device__ double g_sum3[JJ], g_sq3[JJ];

// ---------------- helpers ----------------
__device__ __forceinline__ void cpasync16(void* dst, const void* src) {
    unsigned sa = (unsigned)__cvta_generic_to_shared(dst);
    asm volatile("cp.async.cg.shared.global [%0], [%1], 16;\n" :: "r"(sa), "l"(src));
}
__device__ __forceinline__ void ldm4(uint32_t* r, const __half* p) {
    unsigned a = (unsigned)__cvta_generic_to_shared(p);
    asm volatile("ldmatrix.sync.aligned.m8n8.x4.shared.b16 {%0,%1,%2,%3}, [%4];"
                 : "=r"(r[0]), "=r"(r[1]), "=r"(r[2]), "=r"(r[3]) : "r"(a));
}
__device__ __forceinline__ void mma16816(float* c, const uint32_t* a, uint32_t b0, uint32_t b1) {
    asm volatile("mma.sync.aligned.m16n8k16.row.col.f32.f16.f16.f32 "
                 "{%0,%1,%2,%3},{%4,%5,%6,%7},{%8,%9},{%0,%1,%2,%3};"
                 : "+f"(c[0]), "+f"(c[1]), "+f"(c[2]), "+f"(c[3])
                 : "r"(a[0]), "r"(a[1]), "r"(a[2]), "r"(a[3]), "r"(b0), "r"(b1));
}

// ---------------- prep kernels ----------------
__global__ void prep_x(const float* __restrict__ x)
{
    size_t i = (size_t)blockIdx.x * blockDim.x + threadIdx.x;
    if (i >= (size_t)MM * JJ) return;
    float v = x[i];
    __half hi = __float2half_rn(v);
    g_x0[i] = hi;
    g_x1[i] = __float2half_rn(v - __half2float(hi));
}

__global__ void prep_w(const float* __restrict__ W1, const float* __restrict__ W2,
                       const float* __restrict__ W3)
{
    size_t i = (size_t)blockIdx.x * blockDim.x + threadIdx.x;
    if (i < HH) { g_sum1[i] = 0.0; g_sq1[i] = 0.0; g_sum2[i] = 0.0; g_sq2[i] = 0.0; }
    if (i < JJ) { g_sum3[i] = 0.0; g_sq3[i] = 0.0; }

    const size_t n1 = (size_t)HH * JJ;
    const size_t n2 = (size_t)HH * HH;
    const size_t n3 = (size_t)JJ * HH;
    if (i < n1) {
        float v = W1[i]; __half h = __float2half_rn(v);
        g_w1a[i] = h; g_w1b[i] = __float2half_rn(v - __half2float(h));
    }
    if (i < n2) {
        float v = W2[i]; __half h = __float2half_rn(v);
        g_w2a[i] = h; g_w2b[i] = __float2half_rn(v - __half2float(h));
    }
    if (i < n3) {
        float v = W3[i]; __half h = __float2half_rn(v);
        g_w3a[i] = h; g_w3b[i] = __float2half_rn(v - __half2float(h));
    }
}

// ---------------- GEMM tiles ----------------
#define TSH 40
#define ARRH (128*TSH)
#define ARRB (ARRH*2)

// ======= layer-1 fused: C = A0*(B0+B1)^T + A1*B0^T =======
__global__ __launch_bounds__(256, 2) void gemm_l1(
    const __half* __restrict__ A0g, const __half* __restrict__ A1g,
    const __half* __restrict__ B0g, const __half* __restrict__ B1g,
    float* __restrict__ C, int N, int K)
{
    extern __shared__ __half smem[];
    constexpr uint32_t STAGEB = 4 * ARRB;

    const int tid  = threadIdx.x;
    const int lane = tid & 31;
    const int warp = tid >> 5;
    const int wm   = warp >> 2;
    const int wn   = warp & 3;
    const int bm   = blockIdx.y * 128;
    const int bn   = blockIdx.x * 128;

    const __half* gbase[4];
    gbase[0] = A0g + (size_t)bm * K;
    gbase[1] = A1g + (size_t)bm * K;
    gbase[2] = B0g + (size_t)bn * K;
    gbase[3] = B1g + (size_t)bn * K;

    float acc[4][4][4];
#pragma unroll
    for (int i = 0; i < 4; i++)
#pragma unroll
        for (int j = 0; j < 4; j++)
#pragma unroll
            for (int k = 0; k < 4; k++) acc[i][j][k] = 0.0f;

    const int NK = K >> 5;

    auto load_stage = [&](int kt, int slot) {
        const int kb = kt << 5;
        char* sb = (char*)smem + (uint32_t)slot * STAGEB;
#pragma unroll
        for (int a = 0; a < 4; a++) {
            const __half* g = gbase[a];
            char* sa = sb + a * ARRB;
#pragma unroll
            for (int c = tid; c < 512; c += 256) {
                int r = c >> 2, q = c & 3;
                cpasync16(sa + r * (TSH*2) + q * 16, g + (size_t)r * K + kb + q * 8);
            }
        }
        asm volatile("cp.async.commit_group;");
    };

    load_stage(0, 0);

    for (int kt = 0; kt < NK; kt++) {
        if (kt + 1 < NK) {
            load_stage(kt + 1, (kt + 1) & 1);
            asm volatile("cp.async.wait_group 1;");
        } else {
            asm volatile("cp.async.wait_group 0;");
        }
        __syncthreads();

        const __half* sb = smem + (uint32_t)((kt & 1) * STAGEB / 2);
        const __half* tA0 = sb;
        const __half* tA1 = sb + ARRH;
        const __half* tB0 = sb + 2 * ARRH;
        const __half* tB1 = sb + 3 * ARRH;

#pragma unroll
        for (int k16 = 0; k16 < 32; k16 += 16) {
            const int ra = wm * 64 + (lane & 7) + ((lane >> 3) & 1) * 8;
            const int ka = k16 + (lane >> 4) * 8;
            const int rb = wn * 32 + (lane & 7) + (lane >> 4) * 8;
            const int kb2 = k16 + ((lane >> 3) & 1) * 8;

            uint32_t a0[4][4], a1[4][4], b0[2][4], b1[2][4];
#pragma unroll
            for (int mt = 0; mt < 4; mt++) ldm4(a0[mt], tA0 + (ra + mt * 16) * TSH + ka);
#pragma unroll
            for (int g = 0; g < 2; g++)  ldm4(b0[g], tB0 + (rb + g * 16) * TSH + kb2);
#pragma unroll
            for (int mt = 0; mt < 4; mt++)
#pragma unroll
                for (int nt = 0; nt < 4; nt++)
                    mma16816(acc[mt][nt], a0[mt], b0[nt >> 1][(nt & 1) * 2], b0[nt >> 1][(nt & 1) * 2 + 1]);

#pragma unroll
            for (int mt = 0; mt < 4; mt++) ldm4(a1[mt], tA1 + (ra + mt * 16) * TSH + ka);
#pragma unroll
            for (int mt = 0; mt < 4; mt++)
#pragma unroll
                for (int nt = 0; nt < 4; nt++)
                    mma16816(acc[mt][nt], a1[mt], b0[nt >> 1][(nt & 1) * 2], b0[nt >> 1][(nt & 1) * 2 + 1]);

#pragma unroll
            for (int g = 0; g < 2; g++)  ldm4(b1[g], tB1 + (rb + g * 16) * TSH + kb2);
#pragma unroll
            for (int mt = 0; mt < 4; mt++)
#pragma unroll
                for (int nt = 0; nt < 4; nt++)
                    mma16816(acc[mt][nt], a0[mt], b1[nt >> 1][(nt & 1) * 2], b1[nt >> 1][(nt & 1) * 2 + 1]);
        }
        __syncthreads();
    }

#pragma unroll
    for (int mt = 0; mt < 4; mt++) {
#pragma unroll
        for (int nt = 0; nt < 4; nt++) {
            int row = bm + wm * 64 + mt * 16 + (lane >> 2);
            int col = bn + wn * 32 + nt * 8 + (lane & 3) * 2;
            *(float2*)(C + (size_t)row * N + col)       = make_float2(acc[mt][nt][0], acc[mt][nt][1]);
            *(float2*)(C + (size_t)(row + 8) * N + col) = make_float2(acc[mt][nt][2], acc[mt][nt][3]);
        }
    }
}

// ======= layers 2/3: C = A*(B0+B1)^T, 3-stage =======
__global__ __launch_bounds__(256, 2) void gemm_v2(
    const __half* __restrict__ A, const __half* __restrict__ B0, const __half* __restrict__ B1,
    float* __restrict__ C, int N, int K)
{
    constexpr uint32_t STAGEB = 3 * ARRB;
    extern __shared__ __half smem[];

    const int tid  = threadIdx.x;
    const int lane = tid & 31;
    const int warp = tid >> 5;
    const int wm   = warp >> 2;
    const int wn   = warp & 3;
    const int bm   = blockIdx.y * 128;
    const int bn   = blockIdx.x * 128;

    const __half* gbase[3];
    gbase[0] = A  + (size_t)bm * K;
    gbase[1] = B0 + (size_t)bn * K;
    gbase[2] = B1 + (size_t)bn * K;

    float acc[4][4][4];
#pragma unroll
    for (int i = 0; i < 4; i++)
#pragma unroll
        for (int j = 0; j < 4; j++)
#pragma unroll
            for (int k = 0; k < 4; k++) acc[i][j][k] = 0.0f;

    const int NK = K >> 5;

    auto load_stage = [&](int kt, int slot) {
        const int kb = kt << 5;
        char* sb = (char*)smem + (uint32_t)slot * STAGEB;
#pragma unroll
        for (int a = 0; a < 3; a++) {
            const __half* g = gbase[a];
            char* sa = sb + a * ARRB;
#pragma unroll
            for (int c = tid; c < 512; c += 256) {
                int r = c >> 2, q = c & 3;
                cpasync16(sa + r * (TSH*2) + q * 16, g + (size_t)r * K + kb + q * 8);
            }
        }
        asm volatile("cp.async.commit_group;");
    };

    load_stage(0, 0);
    if (NK > 1) load_stage(1, 1);

    for (int kt = 0; kt < NK; kt++) {
        if (kt + 1 < NK) asm volatile("cp.async.wait_group 1;");
        else             asm volatile("cp.async.wait_group 0;");
        __syncthreads();

        if (kt + 2 < NK) load_stage(kt + 2, (kt + 2) % 3);

        const __half* sb = smem + (uint32_t)((kt % 3) * STAGEB / 2);
        const __half* tA  = sb;
        const __half* tB0 = sb + ARRH;
        const __half* tB1 = sb + 2 * ARRH;

#pragma unroll
        for (int k16 = 0; k16 < 32; k16 += 16) {
            uint32_t af[4][4];
            {
                int r  = wm * 64 + (lane & 7) + ((lane >> 3) & 1) * 8;
                int kc = k16 + (lane >> 4) * 8;
#pragma unroll
                for (int mt = 0; mt < 4; mt++)
                    ldm4(af[mt], tA + (r + mt * 16) * TSH + kc);
            }
#pragma unroll
            for (int p = 0; p < 2; p++) {
                const __half* tB = p ? tB1 : tB0;
                uint32_t bf[2][4];
                {
                    int r  = wn * 32 + (lane & 7) + (lane >> 4) * 8;
                    int kc = k16 + ((lane >> 3) & 1) * 8;
#pragma unroll
                    for (int g = 0; g < 2; g++)
                        ldm4(bf[g], tB + (r + g * 16) * TSH + kc);
                }
#pragma unroll
                for (int mt = 0; mt < 4; mt++)
#pragma unroll
                    for (int nt = 0; nt < 4; nt++)
                        mma16816(acc[mt][nt], af[mt],
                                 bf[nt >> 1][(nt & 1) * 2], bf[nt >> 1][(nt & 1) * 2 + 1]);
            }
        }
    }

#pragma unroll
    for (int mt = 0; mt < 4; mt++) {
#pragma unroll
        for (int nt = 0; nt < 4; nt++) {
            int row = bm + wm * 64 + mt * 16 + (lane >> 2);
            int col = bn + wn * 32 + nt * 8 + (lane & 3) * 2;
            *(float2*)(C + (size_t)row * N + col)       = make_float2(acc[mt][nt][0], acc[mt][nt][1]);
            *(float2*)(C + (size_t)(row + 8) * N + col) = make_float2(acc[mt][nt][2], acc[mt][nt][3]);
        }
    }
}

// ---------------- per-channel stats: fp32 partials, 32 row-chunks ----------------
// grid (I/32, 32), block (32,32). Each thread: 32 fp32 accum; smem tree over ty;
// chunk partial merged into double via atomicAdd (32 atomics per channel).
__global__ void colstats(const float* __restrict__ h, double* __restrict__ sum,
                         double* __restrict__ sq, int rows, int I)
{
    const int tx = threadIdx.x, ty = threadIdx.y;
    const int i = blockIdx.x * 32 + tx;
    const int rchunk = rows >> 5;
    const int r0 = blockIdx.y * rchunk;

    float s = 0.0f, q = 0.0f;
    for (int r = r0 + ty; r < r0 + rchunk; r += 32) {
        float v = h[(size_t)r * I + i];
        s += v;
        q = fmaf(v, v, q);
    }
    __shared__ float sh_s[32][33], sh_q[32][33];
    sh_s[ty][tx] = s; sh_q[ty][tx] = q;
    __syncthreads();
    for (int off = 16; off > 0; off >>= 1) {
        if (ty < off) { sh_s[ty][tx] += sh_s[ty+off][tx]; sh_q[ty][tx] += sh_q[ty+off][tx]; }
        __syncthreads();
    }
    if (ty == 0) {
        atomicAdd(&sum[i], (double)sh_s[0][tx]);
        atomicAdd(&sq[i],  (double)sh_q[0][tx]);
    }
}

// ---------------- BatchNorm + LIF scan (finalizes stats from sums) ----------------
template <typename OutT>
__global__ void lif_scan(const float* __restrict__ h,
                         const double* __restrict__ sum, const double* __restrict__ sq,
                         const float* __restrict__ gamma, const float* __restrict__ bias,
                         const float* __restrict__ betap, const float* __restrict__ U0,
                         OutT* __restrict__ S, int Bn, int T, int I)
{
    int idx = blockIdx.x * blockDim.x + threadIdx.x;
    if (idx >= Bn * I) return;
    int b = idx / I, i = idx - b * I;

    const double inv = 1.0 / (double)(Bn * T);
    double mu_d = sum[i] * inv;
    double var_d = sq[i] * inv - mu_d * mu_d;
    float m = (float)mu_d;
    float rstd = (float)(1.0 / sqrt(var_d + 1e-5));
    float g = gamma[i], bi = bias[i];
    float beta = (float)(1.0 / (1.0 + exp(-(double)betap[i])));
    float ombeta = 1.0f - beta;

    float U = U0[idx], Sv = 0.0f;
    const float* hp = h + (size_t)b * T * I + i;
    OutT* sp = S + (size_t)b * T * I + i;

    for (int t = 0; t < T; t++) {
        float x = ((hp[(size_t)t * I] - m) * rstd) * g + bi;
        U = beta * (U - Sv) + ombeta * x;
        Sv = (U >= 1.0f) ? 1.0f : 0.0f;
        sp[(size_t)t * I] = (OutT)Sv;
    }
}

// ---------------- driver ----------------
extern "C" void kernel_launch(void* const* d_in, const int* in_sizes, int n_in,
                              void* d_out, int out_size)
{
    const float* x      = (const float*)d_in[0];
    const float* W1     = (const float*)d_in[1];
    const float* beta1  = (const float*)d_in[2];
    const float* gamma1 = (const float*)d_in[3];
    const float* bias1  = (const float*)d_in[4];
    const float* U01    = (const float*)d_in[5];
    const float* W2     = (const float*)d_in[6];
    const float* beta2  = (const float*)d_in[7];
    const float* gamma2 = (const float*)d_in[8];
    const float* bias2  = (const float*)d_in[9];
    const float* U02    = (const float*)d_in[10];
    const float* W3     = (const float*)d_in[11];
    const float* beta3  = (const float*)d_in[12];
    const float* gamma3 = (const float*)d_in[13];
    const float* bias3  = (const float*)d_in[14];
    const float* U03    = (const float*)d_in[15];
    float* out = (float*)d_out;

    float *h; __half *s16, *x0, *x1, *w1a, *w1b, *w2a, *w2b, *w3a, *w3b;
    double *sum1, *sq1, *sum2, *sq2, *sum3, *sq3;
    cudaGetSymbolAddress((void**)&h,   g_h);
    cudaGetSymbolAddress((void**)&s16, g_s16);
    cudaGetSymbolAddress((void**)&x0,  g_x0);
    cudaGetSymbolAddress((void**)&x1,  g_x1);
    cudaGetSymbolAddress((void**)&w1a, g_w1a);
    cudaGetSymbolAddress((void**)&w1b, g_w1b);
    cudaGetSymbolAddress((void**)&w2a, g_w2a);
    cudaGetSymbolAddress((void**)&w2b, g_w2b);
    cudaGetSymbolAddress((void**)&w3a, g_w3a);
    cudaGetSymbolAddress((void**)&w3b, g_w3b);
    cudaGetSymbolAddress((void**)&sum1, g_sum1);
    cudaGetSymbolAddress((void**)&sq1,  g_sq1);
    cudaGetSymbolAddress((void**)&sum2, g_sum2);
    cudaGetSymbolAddress((void**)&sq2,  g_sq2);
    cudaGetSymbolAddress((void**)&sum3, g_sum3);
    cudaGetSymbolAddress((void**)&sq3,  g_sq3);

    const int SML1 = 2 * 4 * ARRB;   // 81920 B
    const int SMV2 = 3 * 3 * ARRB;   // 92160 B
    cudaFuncSetAttribute(gemm_l1, cudaFuncAttributeMaxDynamicSharedMemorySize, SML1);
    cudaFuncSetAttribute(gemm_v2, cudaFuncAttributeMaxDynamicSharedMemorySize, SMV2);

    // 0: split x
    prep_x<<<(unsigned)(((size_t)MM * JJ + 255) / 256), 256>>>(x);
    // 1: split W1,W2,W3 + zero stat sums
    prep_w<<<(unsigned)(((size_t)HH * HH + 255) / 256), 256>>>(W1, W2, W3);

    // 2: layer-1 fused GEMM
    gemm_l1<<<dim3(HH / 128, MM / 128), 256, SML1>>>(x0, x1, w1a, w1b, h, HH, JJ);
    // 3,4
    colstats<<<dim3(HH / 32, 32), dim3(32, 32)>>>(h, sum1, sq1, MM, HH);
    lif_scan<__half><<<(BB * HH + 255) / 256, 256>>>(h, sum1, sq1, gamma1, bias1, beta1, U01, s16, BB, TT, HH);

    // 5: layer-2 GEMM (ncu -s 5 captures this)
    gemm_v2<<<dim3(HH / 128, MM / 128), 256, SMV2>>>(s16, w2a, w2b, h, HH, HH);
    // 6,7
    colstats<<<dim3(HH / 32, 32), dim3(32, 32)>>>(h, sum2, sq2, MM, HH);
    lif_scan<__half><<<(BB * HH + 255) / 256, 256>>>(h, sum2, sq2, gamma2, bias2, beta2, U02, s16, BB, TT, HH);

    // 8: layer-3 GEMM
    gemm_v2<<<dim3(JJ / 128, MM / 128), 256, SMV2>>>(s16, w3a, w3b, h, JJ, HH);
    // 9,10
    colstats<<<dim3(JJ / 32, 32), dim3(32, 32)>>>(h, sum3, sq3, MM, JJ);
    lif_scan<float><<<(BB * JJ + 255) / 256, 256>>>(h, sum3, sq3, gamma3, bias3, beta3, U03, out, BB, TT, JJ);
}

// round 9
// speedup vs baseline: 2.2799x; 1.0314x over previous
#include <cuda_runtime.h>
#include <cuda_fp16.h>
#include <math.h>
#include <stdint.h>

// Shapes fixed by dataset: B=32, T=1024, J=1024, H=2048
#define BB 32
#define TT 1024
#define JJ 1024
#define HH 2048
#define MM (BB*TT)   // 32768

// ---------------- scratch ----------------
__device__ float  g_h [(size_t)MM * HH];
__device__ __half g_s16[(size_t)MM * HH];
__device__ __half g_x0[(size_t)MM * JJ];
__device__ __half g_x1[(size_t)MM * JJ];
__device__ __half g_w1a[(size_t)HH * JJ], g_w1b[(size_t)HH * JJ];
__device__ __half g_w2a[(size_t)HH * HH], g_w2b[(size_t)HH * HH];
__device__ __half g_w3a[(size_t)JJ * HH], g_w3b[(size_t)JJ * HH];
__device__ double g_sum1[HH], g_sq1[HH];
__device__ double g_sum2[HH], g_sq2[HH];
__device__ double g_sum3[JJ], g_sq3[JJ];

// ---------------- helpers ----------------
__device__ __forceinline__ void cpasync16(void* dst, const void* src) {
    unsigned sa = (unsigned)__cvta_generic_to_shared(dst);
    asm volatile("cp.async.cg.shared.global [%0], [%1], 16;\n" :: "r"(sa), "l"(src));
}
__device__ __forceinline__ void ldm4(uint32_t* r, const __half* p) {
    unsigned a = (unsigned)__cvta_generic_to_shared(p);
    asm volatile("ldmatrix.sync.aligned.m8n8.x4.shared.b16 {%0,%1,%2,%3}, [%4];"
                 : "=r"(r[0]), "=r"(r[1]), "=r"(r[2]), "=r"(r[3]) : "r"(a));
}
__device__ __forceinline__ void mma16816(float* c, const uint32_t* a, uint32_t b0, uint32_t b1) {
    asm volatile("mma.sync.aligned.m16n8k16.row.col.f32.f16.f16.f32 "
                 "{%0,%1,%2,%3},{%4,%5,%6,%7},{%8,%9},{%0,%1,%2,%3};"
                 : "+f"(c[0]), "+f"(c[1]), "+f"(c[2]), "+f"(c[3])
                 : "r"(a[0]), "r"(a[1]), "r"(a[2]), "r"(a[3]), "r"(b0), "r"(b1));
}

// ---------------- prep: split x + all weights, zero stat sums ----------------
__global__ void prep_all(const float* __restrict__ x, const float* __restrict__ W1,
                         const float* __restrict__ W2, const float* __restrict__ W3)
{
    size_t i = (size_t)blockIdx.x * blockDim.x + threadIdx.x;
    if (i < HH) { g_sum1[i] = 0.0; g_sq1[i] = 0.0; g_sum2[i] = 0.0; g_sq2[i] = 0.0; }
    if (i < JJ) { g_sum3[i] = 0.0; g_sq3[i] = 0.0; }

    if (i < (size_t)MM * JJ) {
        float v = x[i];
        __half hi = __float2half_rn(v);
        g_x0[i] = hi;
        g_x1[i] = __float2half_rn(v - __half2float(hi));
    }
    if (i < (size_t)HH * JJ) {
        float v = W1[i]; __half h = __float2half_rn(v);
        g_w1a[i] = h; g_w1b[i] = __float2half_rn(v - __half2float(h));
    }
    if (i < (size_t)HH * HH) {
        float v = W2[i]; __half h = __float2half_rn(v);
        g_w2a[i] = h; g_w2b[i] = __float2half_rn(v - __half2float(h));
    }
    if (i < (size_t)JJ * HH) {
        float v = W3[i]; __half h = __float2half_rn(v);
        g_w3a[i] = h; g_w3b[i] = __float2half_rn(v - __half2float(h));
    }
}

// ---------------- shared epilogue: store C tile + fused column stats ----------------
__device__ __forceinline__ void epilogue_stats(
    float acc[4][4][4], float* __restrict__ C, double* __restrict__ sum, double* __restrict__ sq,
    int N, int bm, int bn, int wm, int wn, int lane)
{
#pragma unroll
    for (int mt = 0; mt < 4; mt++) {
#pragma unroll
        for (int nt = 0; nt < 4; nt++) {
            int row = bm + wm * 64 + mt * 16 + (lane >> 2);
            int col = bn + wn * 32 + nt * 8 + (lane & 3) * 2;
            *(float2*)(C + (size_t)row * N + col)       = make_float2(acc[mt][nt][0], acc[mt][nt][1]);
            *(float2*)(C + (size_t)(row + 8) * N + col) = make_float2(acc[mt][nt][2], acc[mt][nt][3]);
        }
    }
    // fused per-column partial stats over this warp's 64 rows
#pragma unroll
    for (int nt = 0; nt < 4; nt++) {
        float s0 = 0.f, q0 = 0.f, s1 = 0.f, q1 = 0.f;
#pragma unroll
        for (int mt = 0; mt < 4; mt++) {
            float a0 = acc[mt][nt][0], a1 = acc[mt][nt][1];
            float a2 = acc[mt][nt][2], a3 = acc[mt][nt][3];
            s0 += a0 + a2;  q0 += a0 * a0 + a2 * a2;
            s1 += a1 + a3;  q1 += a1 * a1 + a3 * a3;
        }
#pragma unroll
        for (int off = 16; off >= 4; off >>= 1) {
            s0 += __shfl_down_sync(0xffffffffu, s0, off);
            q0 += __shfl_down_sync(0xffffffffu, q0, off);
            s1 += __shfl_down_sync(0xffffffffu, s1, off);
            q1 += __shfl_down_sync(0xffffffffu, q1, off);
        }
        if (lane < 4) {
            int col = bn + wn * 32 + nt * 8 + lane * 2;
            atomicAdd(&sum[col],     (double)s0);
            atomicAdd(&sq[col],      (double)q0);
            atomicAdd(&sum[col + 1], (double)s1);
            atomicAdd(&sq[col + 1],  (double)q1);
        }
    }
}

// ---------------- GEMM tiles ----------------
#define TSH 40
#define ARRH (128*TSH)
#define ARRB (ARRH*2)

// ======= layer-1 fused: C = A0*(B0+B1)^T + A1*B0^T =======
__global__ __launch_bounds__(256, 2) void gemm_l1(
    const __half* __restrict__ A0g, const __half* __restrict__ A1g,
    const __half* __restrict__ B0g, const __half* __restrict__ B1g,
    float* __restrict__ C, double* __restrict__ sum, double* __restrict__ sq,
    int N, int K)
{
    extern __shared__ __half smem[];
    constexpr uint32_t STAGEB = 4 * ARRB;

    const int tid  = threadIdx.x;
    const int lane = tid & 31;
    const int warp = tid >> 5;
    const int wm   = warp >> 2;
    const int wn   = warp & 3;
    const int bm   = blockIdx.y * 128;
    const int bn   = blockIdx.x * 128;

    const __half* gbase[4];
    gbase[0] = A0g + (size_t)bm * K;
    gbase[1] = A1g + (size_t)bm * K;
    gbase[2] = B0g + (size_t)bn * K;
    gbase[3] = B1g + (size_t)bn * K;

    float acc[4][4][4];
#pragma unroll
    for (int i = 0; i < 4; i++)
#pragma unroll
        for (int j = 0; j < 4; j++)
#pragma unroll
            for (int k = 0; k < 4; k++) acc[i][j][k] = 0.0f;

    const int NK = K >> 5;

    auto load_stage = [&](int kt, int slot) {
        const int kb = kt << 5;
        char* sb = (char*)smem + (uint32_t)slot * STAGEB;
#pragma unroll
        for (int a = 0; a < 4; a++) {
            const __half* g = gbase[a];
            char* sa = sb + a * ARRB;
#pragma unroll
            for (int c = tid; c < 512; c += 256) {
                int r = c >> 2, q = c & 3;
                cpasync16(sa + r * (TSH*2) + q * 16, g + (size_t)r * K + kb + q * 8);
            }
        }
        asm volatile("cp.async.commit_group;");
    };

    load_stage(0, 0);

    for (int kt = 0; kt < NK; kt++) {
        if (kt + 1 < NK) {
            load_stage(kt + 1, (kt + 1) & 1);
            asm volatile("cp.async.wait_group 1;");
        } else {
            asm volatile("cp.async.wait_group 0;");
        }
        __syncthreads();

        const __half* sb = smem + (uint32_t)((kt & 1) * STAGEB / 2);
        const __half* tA0 = sb;
        const __half* tA1 = sb + ARRH;
        const __half* tB0 = sb + 2 * ARRH;
        const __half* tB1 = sb + 3 * ARRH;

#pragma unroll
        for (int k16 = 0; k16 < 32; k16 += 16) {
            const int ra = wm * 64 + (lane & 7) + ((lane >> 3) & 1) * 8;
            const int ka = k16 + (lane >> 4) * 8;
            const int rb = wn * 32 + (lane & 7) + (lane >> 4) * 8;
            const int kb2 = k16 + ((lane >> 3) & 1) * 8;

            uint32_t a0[4][4], a1[4][4], b0[2][4], b1[2][4];
#pragma unroll
            for (int mt = 0; mt < 4; mt++) ldm4(a0[mt], tA0 + (ra + mt * 16) * TSH + ka);
#pragma unroll
            for (int g = 0; g < 2; g++)  ldm4(b0[g], tB0 + (rb + g * 16) * TSH + kb2);
#pragma unroll
            for (int mt = 0; mt < 4; mt++)
#pragma unroll
                for (int nt = 0; nt < 4; nt++)
                    mma16816(acc[mt][nt], a0[mt], b0[nt >> 1][(nt & 1) * 2], b0[nt >> 1][(nt & 1) * 2 + 1]);

#pragma unroll
            for (int mt = 0; mt < 4; mt++) ldm4(a1[mt], tA1 + (ra + mt * 16) * TSH + ka);
#pragma unroll
            for (int mt = 0; mt < 4; mt++)
#pragma unroll
                for (int nt = 0; nt < 4; nt++)
                    mma16816(acc[mt][nt], a1[mt], b0[nt >> 1][(nt & 1) * 2], b0[nt >> 1][(nt & 1) * 2 + 1]);

#pragma unroll
            for (int g = 0; g < 2; g++)  ldm4(b1[g], tB1 + (rb + g * 16) * TSH + kb2);
#pragma unroll
            for (int mt = 0; mt < 4; mt++)
#pragma unroll
                for (int nt = 0; nt < 4; nt++)
                    mma16816(acc[mt][nt], a0[mt], b1[nt >> 1][(nt & 1) * 2], b1[nt >> 1][(nt & 1) * 2 + 1]);
        }
        __syncthreads();
    }

    epilogue_stats(acc, C, sum, sq, N, bm, bn, wm, wn, lane);
}

// ======= layers 2/3: C = A*(B0+B1)^T, 3-stage =======
__global__ __launch_bounds__(256, 2) void gemm_v2(
    const __half* __restrict__ A, const __half* __restrict__ B0, const __half* __restrict__ B1,
    float* __restrict__ C, double* __restrict__ sum, double* __restrict__ sq,
    int N, int K)
{
    constexpr uint32_t STAGEB = 3 * ARRB;
    extern __shared__ __half smem[];

    const int tid  = threadIdx.x;
    const int lane = tid & 31;
    const int warp = tid >> 5;
    const int wm   = warp >> 2;
    const int wn   = warp & 3;
    const int bm   = blockIdx.y * 128;
    const int bn   = blockIdx.x * 128;

    const __half* gbase[3];
    gbase[0] = A  + (size_t)bm * K;
    gbase[1] = B0 + (size_t)bn * K;
    gbase[2] = B1 + (size_t)bn * K;

    float acc[4][4][4];
#pragma unroll
    for (int i = 0; i < 4; i++)
#pragma unroll
        for (int j = 0; j < 4; j++)
#pragma unroll
            for (int k = 0; k < 4; k++) acc[i][j][k] = 0.0f;

    const int NK = K >> 5;

    auto load_stage = [&](int kt, int slot) {
        const int kb = kt << 5;
        char* sb = (char*)smem + (uint32_t)slot * STAGEB;
#pragma unroll
        for (int a = 0; a < 3; a++) {
            const __half* g = gbase[a];
            char* sa = sb + a * ARRB;
#pragma unroll
            for (int c = tid; c < 512; c += 256) {
                int r = c >> 2, q = c & 3;
                cpasync16(sa + r * (TSH*2) + q * 16, g + (size_t)r * K + kb + q * 8);
            }
        }
        asm volatile("cp.async.commit_group;");
    };

    load_stage(0, 0);
    if (NK > 1) load_stage(1, 1);

    for (int kt = 0; kt < NK; kt++) {
        if (kt + 1 < NK) asm volatile("cp.async.wait_group 1;");
        else             asm volatile("cp.async.wait_group 0;");
        __syncthreads();

        if (kt + 2 < NK) load_stage(kt + 2, (kt + 2) % 3);

        const __half* sb = smem + (uint32_t)((kt % 3) * STAGEB / 2);
        const __half* tA  = sb;
        const __half* tB0 = sb + ARRH;
        const __half* tB1 = sb + 2 * ARRH;

#pragma unroll
        for (int k16 = 0; k16 < 32; k16 += 16) {
            uint32_t af[4][4];
            {
                int r  = wm * 64 + (lane & 7) + ((lane >> 3) & 1) * 8;
                int kc = k16 + (lane >> 4) * 8;
#pragma unroll
                for (int mt = 0; mt < 4; mt++)
                    ldm4(af[mt], tA + (r + mt * 16) * TSH + kc);
            }
#pragma unroll
            for (int p = 0; p < 2; p++) {
                const __half* tB = p ? tB1 : tB0;
                uint32_t bf[2][4];
                {
                    int r  = wn * 32 + (lane & 7) + (lane >> 4) * 8;
                    int kc = k16 + ((lane >> 3) & 1) * 8;
#pragma unroll
                    for (int g = 0; g < 2; g++)
                        ldm4(bf[g], tB + (r + g * 16) * TSH + kc);
                }
#pragma unroll
                for (int mt = 0; mt < 4; mt++)
#pragma unroll
                    for (int nt = 0; nt < 4; nt++)
                        mma16816(acc[mt][nt], af[mt],
                                 bf[nt >> 1][(nt & 1) * 2], bf[nt >> 1][(nt & 1) * 2 + 1]);
            }
        }
    }

    epilogue_stats(acc, C, sum, sq, N, bm, bn, wm, wn, lane);
}

// ---------------- BatchNorm + LIF scan (finalizes stats from sums) ----------------
template <typename OutT>
__global__ void lif_scan(const float* __restrict__ h,
                         const double* __restrict__ sum, const double* __restrict__ sq,
                         const float* __restrict__ gamma, const float* __restrict__ bias,
                         const float* __restrict__ betap, const float* __restrict__ U0,
                         OutT* __restrict__ S, int Bn, int T, int I)
{
    int idx = blockIdx.x * blockDim.x + threadIdx.x;
    if (idx >= Bn * I) return;
    int b = idx / I, i = idx - b * I;

    const double inv = 1.0 / (double)(Bn * T);
    double mu_d = sum[i] * inv;
    double var_d = sq[i] * inv - mu_d * mu_d;
    float m = (float)mu_d;
    float rstd = (float)(1.0 / sqrt(var_d + 1e-5));
    float g = gamma[i], bi = bias[i];
    float beta = (float)(1.0 / (1.0 + exp(-(double)betap[i])));
    float ombeta = 1.0f - beta;

    float U = U0[idx], Sv = 0.0f;
    const float* hp = h + (size_t)b * T * I + i;
    OutT* sp = S + (size_t)b * T * I + i;

    for (int t = 0; t < T; t++) {
        float x = ((hp[(size_t)t * I] - m) * rstd) * g + bi;
        U = beta * (U - Sv) + ombeta * x;
        Sv = (U >= 1.0f) ? 1.0f : 0.0f;
        sp[(size_t)t * I] = (OutT)Sv;
    }
}

// ---------------- driver ----------------
extern "C" void kernel_launch(void* const* d_in, const int* in_sizes, int n_in,
                              void* d_out, int out_size)
{
    const float* x      = (const float*)d_in[0];
    const float* W1     = (const float*)d_in[1];
    const float* beta1  = (const float*)d_in[2];
    const float* gamma1 = (const float*)d_in[3];
    const float* bias1  = (const float*)d_in[4];
    const float* U01    = (const float*)d_in[5];
    const float* W2     = (const float*)d_in[6];
    const float* beta2  = (const float*)d_in[7];
    const float* gamma2 = (const float*)d_in[8];
    const float* bias2  = (const float*)d_in[9];
    const float* U02    = (const float*)d_in[10];
    const float* W3     = (const float*)d_in[11];
    const float* beta3  = (const float*)d_in[12];
    const float* gamma3 = (const float*)d_in[13];
    const float* bias3  = (const float*)d_in[14];
    const float* U03    = (const float*)d_in[15];
    float* out = (float*)d_out;

    float *h; __half *s16, *x0, *x1, *w1a, *w1b, *w2a, *w2b, *w3a, *w3b;
    double *sum1, *sq1, *sum2, *sq2, *sum3, *sq3;
    cudaGetSymbolAddress((void**)&h,   g_h);
    cudaGetSymbolAddress((void**)&s16, g_s16);
    cudaGetSymbolAddress((void**)&x0,  g_x0);
    cudaGetSymbolAddress((void**)&x1,  g_x1);
    cudaGetSymbolAddress((void**)&w1a, g_w1a);
    cudaGetSymbolAddress((void**)&w1b, g_w1b);
    cudaGetSymbolAddress((void**)&w2a, g_w2a);
    cudaGetSymbolAddress((void**)&w2b, g_w2b);
    cudaGetSymbolAddress((void**)&w3a, g_w3a);
    cudaGetSymbolAddress((void**)&w3b, g_w3b);
    cudaGetSymbolAddress((void**)&sum1, g_sum1);
    cudaGetSymbolAddress((void**)&sq1,  g_sq1);
    cudaGetSymbolAddress((void**)&sum2, g_sum2);
    cudaGetSymbolAddress((void**)&sq2,  g_sq2);
    cudaGetSymbolAddress((void**)&sum3, g_sum3);
    cudaGetSymbolAddress((void**)&sq3,  g_sq3);

    const int SML1 = 2 * 4 * ARRB;   // 81920 B
    const int SMV2 = 3 * 3 * ARRB;   // 92160 B
    cudaFuncSetAttribute(gemm_l1, cudaFuncAttributeMaxDynamicSharedMemorySize, SML1);
    cudaFuncSetAttribute(gemm_v2, cudaFuncAttributeMaxDynamicSharedMemorySize, SMV2);

    // 0: prep everything (splits + zero sums)
    prep_all<<<(unsigned)(((size_t)MM * JJ + 255) / 256), 256>>>(x, W1, W2, W3);

    // 1: layer-1 fused GEMM (+stats)
    gemm_l1<<<dim3(HH / 128, MM / 128), 256, SML1>>>(x0, x1, w1a, w1b, h, sum1, sq1, HH, JJ);
    // 2: lif 1
    lif_scan<__half><<<(BB * HH + 255) / 256, 256>>>(h, sum1, sq1, gamma1, bias1, beta1, U01, s16, BB, TT, HH);

    // 3: layer-2 GEMM (+stats)  <-- ncu captures this
    gemm_v2<<<dim3(HH / 128, MM / 128), 256, SMV2>>>(s16, w2a, w2b, h, sum2, sq2, HH, HH);
    // 4: lif 2
    lif_scan<__half><<<(BB * HH + 255) / 256, 256>>>(h, sum2, sq2, gamma2, bias2, beta2, U02, s16, BB, TT, HH);

    // 5: layer-3 GEMM (+stats)
    gemm_v2<<<dim3(JJ / 128, MM / 128), 256, SMV2>>>(s16, w3a, w3b, h, sum3, sq3, JJ, HH);
    // 6: lif 3
    lif_scan<float><<<(BB * JJ + 255) / 256, 256>>>(h, sum3, sq3, gamma3, bias3, beta3, U03, out, BB, TT, JJ);
}